// round 5
// baseline (speedup 1.0000x reference)
#include <cuda_runtime.h>
#include <math.h>

// Problem constants
#define Bq 128
#define Tq 160
#define Fq 512
#define Eq 64
#define Hq 1024
#define IN0q (Fq + Eq)   // 576

// -------------------- persistent scratch (device globals, no allocs) --------------------
__device__ float g_h0[Tq * Bq * Hq];   // layer-0 hidden per timestep  (84 MB)
__device__ float g_h1[Tq * Bq * Hq];   // layer-1 hidden per timestep  (84 MB)
__device__ float g_c0[Bq * Hq];        // layer-0 cell state (current)
__device__ float g_c1[Bq * Hq];        // layer-1 cell state (current)
__device__ unsigned char g_mask[Bq * Tq];  // canonical uint8 mask

__device__ __forceinline__ float sigmoidf_(float x) { return 1.0f / (1.0f + expf(-x)); }

// -------------------- mask dtype detection + normalization --------------------
// The harness may hand us the JAX bool mask as uint8 (1B), int32, or float32 (4B).
// Detection: over the first 4096 bytes, bytes at offsets == 1 (mod 4) are always
// zero for int32 0/1 (01 00 00 00) and float32 0.0/1.0 (00 00 80 3f), but are
// nonzero ~30% of the time for a dense uint8 Bernoulli(0.3) mask. Any nonzero
// sample => 1-byte layout.  (Buffer is >= Bq*Tq bytes in all cases, so the
// 4096-byte probe window never reads out of bounds.)
__global__ void mask_norm_kernel(const unsigned char* __restrict__ m_raw)
{
    __shared__ int s_is_u8;
    int tid = threadIdx.x;
    if (tid == 0) s_is_u8 = 0;
    __syncthreads();
    // probe: 1024 samples at byte offsets 4*i + 1
    for (int i = tid; i < 1024; i += blockDim.x) {
        if (m_raw[4 * i + 1] != 0) atomicOr(&s_is_u8, 1);
    }
    __syncthreads();
    const int is_u8 = s_is_u8;
    const unsigned int* m32 = reinterpret_cast<const unsigned int*>(m_raw);
    for (int i = tid; i < Bq * Tq; i += blockDim.x) {
        unsigned char v;
        if (is_u8) v = (m_raw[i] != 0) ? 1 : 0;
        else       v = (m32[i] != 0u) ? 1 : 0;   // works for int32 1 and float32 1.0f
        g_mask[i] = v;
    }
}

// Shared layout:
//   xs[b*33 + k]  : 64 b-rows x 32 k (pad 33 -> conflict-free LDS/STS)
//   ws[k*65 + n]  : 32 k-rows x 64 n (pad 65 -> conflict-free LDS/STS)
struct SmemT {
    float xs[64 * 33];
    float ws[32 * 65];
    float mu_s[64];
    unsigned char um_s[64];
};

// One GEMM phase: acc[b_i][gate] += x[b][k] * W[gate*H + j0 + jj][k]
// CTA tile: 64 b x (16 jj x 4 gates), K = kcols (multiple of 32).
// x source: either a global row-major array (base + b*stride + k), or the "label"
// segment built on the fly: use_mu ? mu[b]*W_tgt[k] + b_tgt[k] : emb[b][k].
__device__ __forceinline__ void gemm_phase(
    float (&acc)[8][4],
    const float* __restrict__ xbase, int xstride,
    int lab_mode,
    const float* __restrict__ emb_base, int emb_stride,
    const float* __restrict__ Wt, const float* __restrict__ bt,
    const float* __restrict__ W, int ldW, int kcols,
    int b0, int j0, int tid, int tx, int ty,
    SmemT* sm)
{
    const int ntiles = kcols >> 5;
    float xr[16], wr[16];

    auto load_tile = [&](int kt) {
        const int k0 = kt << 5;
#pragma unroll
        for (int r = 0; r < 16; ++r) {
            int idx = tid + (r << 7);       // 128 threads x 16 = 2048 elems
            int k = idx & 31;
            int q = idx >> 5;               // b for x, n for w
            int kg = k0 + k;
            float xv;
            if (!lab_mode) {
                xv = xbase[(b0 + q) * xstride + kg];
            } else {
                if (sm->um_s[q]) xv = fmaf(sm->mu_s[q], Wt[kg], bt[kg]);
                else             xv = emb_base[(b0 + q) * emb_stride + kg];
            }
            xr[r] = xv;
            int g = q >> 4, jj = q & 15;
            wr[r] = W[(g * Hq + j0 + jj) * ldW + kg];
        }
    };

    load_tile(0);
    for (int kt = 0; kt < ntiles; ++kt) {
        __syncthreads();
#pragma unroll
        for (int r = 0; r < 16; ++r) {
            int idx = tid + (r << 7);
            int k = idx & 31;
            int q = idx >> 5;
            sm->xs[q * 33 + k] = xr[r];
            sm->ws[k * 65 + q] = wr[r];
        }
        __syncthreads();
        if (kt + 1 < ntiles) load_tile(kt + 1);  // overlap next-tile loads with compute
#pragma unroll
        for (int k = 0; k < 32; ++k) {
            float xv[8];
#pragma unroll
            for (int i = 0; i < 8; ++i) xv[i] = sm->xs[(ty * 8 + i) * 33 + k];
#pragma unroll
            for (int g = 0; g < 4; ++g) {
                float wv = sm->ws[k * 65 + g * 16 + tx];
#pragma unroll
                for (int i = 0; i < 8; ++i) acc[i][g] = fmaf(xv[i], wv, acc[i][g]);
            }
        }
    }
}

// Fused epilogue: add biases, LSTM cell update, write c-state and h.
__device__ __forceinline__ void lstm_epilogue(
    float (&acc)[8][4],
    const float* __restrict__ b_ih, const float* __restrict__ b_hh,
    float* __restrict__ c_state, float* __restrict__ h_arr,
    int t, int b0, int j0, int tx, int ty)
{
    float bsum[4];
#pragma unroll
    for (int g = 0; g < 4; ++g) {
        int row = g * Hq + j0 + tx;
        bsum[g] = b_ih[row] + b_hh[row];
    }
    int j = j0 + tx;
#pragma unroll
    for (int i = 0; i < 8; ++i) {
        int bg = b0 + ty * 8 + i;
        float gi = acc[i][0] + bsum[0];
        float gf = acc[i][1] + bsum[1];
        float gg = acc[i][2] + bsum[2];
        float go = acc[i][3] + bsum[3];
        int cidx = bg * Hq + j;
        float cp = (t == 0) ? 0.0f : c_state[cidx];
        float c = sigmoidf_(gf) * cp + sigmoidf_(gi) * tanhf(gg);
        float h = sigmoidf_(go) * tanhf(c);
        c_state[cidx] = c;
        h_arr[(t * Bq + bg) * Hq + j] = h;
    }
}

// ----------------------------- layer-0 cell (one timestep) -----------------------------
__global__ void __launch_bounds__(128) cell0_kernel(
    const float* __restrict__ feat, const float* __restrict__ emb,
    const float* __restrict__ W_ih0, const float* __restrict__ W_hh0,
    const float* __restrict__ b_ih0, const float* __restrict__ b_hh0,
    const float* __restrict__ W_tgt, const float* __restrict__ b_tgt,
    const float* __restrict__ mu_w, const float* __restrict__ mu_b, int t)
{
    __shared__ SmemT sm;
    int tid = threadIdx.x;
    int tx = tid & 15, ty = tid >> 4;
    int jb = blockIdx.x & 63;
    int b0 = (blockIdx.x >> 6) * 64;
    int j0 = jb * 16;

    // use-mu flags for this CTA's 64 batch rows (canonical uint8 mask)
    if (tid < 64) {
        bool um = (t > 0) && (g_mask[(b0 + tid) * Tq + t] != 0);
        sm.um_s[tid] = um ? 1 : 0;
        // NOTE: no zero-init of mu_s here — for t>0 all 64 entries are written
        // by the warp loop below (before the single __syncthreads), and for
        // t==0 mu_s is never read (um_s==0). A concurrent zero-init raced with
        // the warp writes and corrupted the fed-back mu values.
    }

    // mu[b] from previous step's hidden state: hp[b, 2h+l] = h_l[b][h]
    if (t > 0) {
        int wid = tid >> 5, lane = tid & 31;
        const float2* mw2 = reinterpret_cast<const float2*>(mu_w);
        for (int bi = wid; bi < 64; bi += 4) {
            int bg = b0 + bi;
            const float* h0r = g_h0 + ((t - 1) * Bq + bg) * Hq;
            const float* h1r = g_h1 + ((t - 1) * Bq + bg) * Hq;
            float p = 0.0f;
            for (int h = lane; h < Hq; h += 32) {
                float2 m = mw2[h];
                p = fmaf(h0r[h], m.x, p);
                p = fmaf(h1r[h], m.y, p);
            }
#pragma unroll
            for (int o = 16; o; o >>= 1) p += __shfl_xor_sync(0xffffffffu, p, o);
            if (lane == 0) sm.mu_s[bi] = p + mu_b[0];
        }
    }
    __syncthreads();

    float acc[8][4];
#pragma unroll
    for (int i = 0; i < 8; ++i)
#pragma unroll
        for (int g = 0; g < 4; ++g) acc[i][g] = 0.0f;

    // phase A1: feat part  (K = 512), x[b][k] = feat[b][t][k]
    gemm_phase(acc, feat + t * Fq, Tq * Fq, 0, nullptr, 0, nullptr, nullptr,
               W_ih0, IN0q, Fq, b0, j0, tid, tx, ty, &sm);
    // phase A2: label part (K = 64), built on the fly from mask/mu/W_tgt/b_tgt or labels
    gemm_phase(acc, nullptr, 0, 1, emb + t * Eq, Tq * Eq, W_tgt, b_tgt,
               W_ih0 + Fq, IN0q, Eq, b0, j0, tid, tx, ty, &sm);
    // phase B: recurrent part (K = 1024), x = h0(t-1); h0(-1) = 0 -> skip
    if (t > 0)
        gemm_phase(acc, g_h0 + (t - 1) * Bq * Hq, Hq, 0, nullptr, 0, nullptr, nullptr,
                   W_hh0, Hq, Hq, b0, j0, tid, tx, ty, &sm);

    lstm_epilogue(acc, b_ih0, b_hh0, g_c0, g_h0, t, b0, j0, tx, ty);
}

// ----------------------------- layer-1 cell (one timestep) -----------------------------
__global__ void __launch_bounds__(128) cell1_kernel(
    const float* __restrict__ W_ih1, const float* __restrict__ W_hh1,
    const float* __restrict__ b_ih1, const float* __restrict__ b_hh1, int t)
{
    __shared__ SmemT sm;
    int tid = threadIdx.x;
    int tx = tid & 15, ty = tid >> 4;
    int jb = blockIdx.x & 63;
    int b0 = (blockIdx.x >> 6) * 64;
    int j0 = jb * 16;

    float acc[8][4];
#pragma unroll
    for (int i = 0; i < 8; ++i)
#pragma unroll
        for (int g = 0; g < 4; ++g) acc[i][g] = 0.0f;

    // phase A: x = h0(t)  (just written by cell0 for this step)
    gemm_phase(acc, g_h0 + t * Bq * Hq, Hq, 0, nullptr, 0, nullptr, nullptr,
               W_ih1, Hq, Hq, b0, j0, tid, tx, ty, &sm);
    // phase B: x = h1(t-1)
    if (t > 0)
        gemm_phase(acc, g_h1 + (t - 1) * Bq * Hq, Hq, 0, nullptr, 0, nullptr, nullptr,
                   W_hh1, Hq, Hq, b0, j0, tid, tx, ty, &sm);

    lstm_epilogue(acc, b_ih1, b_hh1, g_c1, g_h1, t, b0, j0, tx, ty);
}

// -------------------- final outputs: mu/sigma for all (b, t) in parallel --------------------
__global__ void out_kernel(
    const float* __restrict__ mu_w, const float* __restrict__ mu_b,
    const float* __restrict__ sig_w, const float* __restrict__ sig_b,
    float* __restrict__ out)
{
    int t = blockIdx.x;
    int wid = threadIdx.x >> 5, lane = threadIdx.x & 31;
    const float2* mw2 = reinterpret_cast<const float2*>(mu_w);
    const float2* sw2 = reinterpret_cast<const float2*>(sig_w);
    for (int b = wid; b < Bq; b += 8) {
        const float* h0r = g_h0 + (t * Bq + b) * Hq;
        const float* h1r = g_h1 + (t * Bq + b) * Hq;
        float mp = 0.0f, sp = 0.0f;
        for (int h = lane; h < Hq; h += 32) {
            float a = h0r[h], c = h1r[h];
            float2 m = mw2[h];
            float2 s = sw2[h];
            mp = fmaf(a, m.x, fmaf(c, m.y, mp));
            sp = fmaf(a, s.x, fmaf(c, s.y, sp));
        }
#pragma unroll
        for (int o = 16; o; o >>= 1) {
            mp += __shfl_xor_sync(0xffffffffu, mp, o);
            sp += __shfl_xor_sync(0xffffffffu, sp, o);
        }
        if (lane == 0) {
            float mu = mp + mu_b[0];
            float sv = sp + sig_b[0];
            // stable softplus matching jax.nn.softplus
            float sig = fmaxf(sv, 0.0f) + log1pf(expf(-fabsf(sv)));
            out[(b * Tq + t) * 2 + 0] = mu;
            out[(b * Tq + t) * 2 + 1] = sig;
        }
    }
}

// ----------------------------------- launch -----------------------------------
extern "C" void kernel_launch(void* const* d_in, const int* in_sizes, int n_in,
                              void* d_out, int out_size)
{
    const float* feat  = (const float*)d_in[0];
    const float* emb   = (const float*)d_in[1];
    const unsigned char* mask_raw = (const unsigned char*)d_in[2];
    const float* W_ih0 = (const float*)d_in[3];
    const float* W_hh0 = (const float*)d_in[4];
    const float* b_ih0 = (const float*)d_in[5];
    const float* b_hh0 = (const float*)d_in[6];
    const float* W_ih1 = (const float*)d_in[7];
    const float* W_hh1 = (const float*)d_in[8];
    const float* b_ih1 = (const float*)d_in[9];
    const float* b_hh1 = (const float*)d_in[10];
    const float* W_tgt = (const float*)d_in[11];
    const float* b_tgt = (const float*)d_in[12];
    const float* mu_w  = (const float*)d_in[13];
    const float* mu_b  = (const float*)d_in[14];
    const float* sig_w = (const float*)d_in[15];
    const float* sig_b = (const float*)d_in[16];
    float* out = (float*)d_out;

    mask_norm_kernel<<<1, 1024>>>(mask_raw);
    for (int t = 0; t < Tq; ++t) {
        cell0_kernel<<<128, 128>>>(feat, emb, W_ih0, W_hh0, b_ih0, b_hh0,
                                   W_tgt, b_tgt, mu_w, mu_b, t);
        cell1_kernel<<<128, 128>>>(W_ih1, W_hh1, b_ih1, b_hh1, t);
    }
    out_kernel<<<Tq, 256>>>(mu_w, mu_b, sig_w, sig_b, out);
}

// round 6
// speedup vs baseline: 1.0308x; 1.0308x over previous
#include <cuda_runtime.h>
#include <math.h>

// Problem constants
#define Bq 128
#define Tq 160
#define Fq 512
#define Eq 64
#define Hq 1024
#define IN0q (Fq + Eq)   // 576

// -------------------- persistent scratch (device globals, no allocs) --------------------
__device__ float g_h0[Tq * Bq * Hq];   // layer-0 hidden per timestep  (84 MB)
__device__ float g_h1[Tq * Bq * Hq];   // layer-1 hidden per timestep  (84 MB)
__device__ float g_c0[Bq * Hq];        // layer-0 cell state (current)
__device__ float g_c1[Bq * Hq];        // layer-1 cell state (current)
__device__ unsigned char g_mask[Bq * Tq];  // canonical uint8 mask

__device__ __forceinline__ float sigmoidf_(float x) { return 1.0f / (1.0f + expf(-x)); }

// -------------------- mask dtype detection + normalization --------------------
// The harness may hand us the JAX bool mask as uint8 (1B), int32, or float32 (4B).
// Detection: over the first 4096 bytes, bytes at offsets == 1 (mod 4) are always
// zero for int32 0/1 (01 00 00 00) and float32 0.0/1.0 (00 00 80 3f), but are
// nonzero ~30% of the time for a dense uint8 Bernoulli(0.3) mask. Any nonzero
// sample => 1-byte layout.  (Buffer is >= Bq*Tq bytes in all cases, so the
// 4096-byte probe window never reads out of bounds.)
__global__ void mask_norm_kernel(const unsigned char* __restrict__ m_raw)
{
    __shared__ int s_is_u8;
    int tid = threadIdx.x;
    if (tid == 0) s_is_u8 = 0;
    __syncthreads();
    // probe: 1024 samples at byte offsets 4*i + 1
    for (int i = tid; i < 1024; i += blockDim.x) {
        if (m_raw[4 * i + 1] != 0) atomicOr(&s_is_u8, 1);
    }
    __syncthreads();
    const int is_u8 = s_is_u8;
    const unsigned int* m32 = reinterpret_cast<const unsigned int*>(m_raw);
    for (int i = tid; i < Bq * Tq; i += blockDim.x) {
        unsigned char v;
        if (is_u8) v = (m_raw[i] != 0) ? 1 : 0;
        else       v = (m32[i] != 0u) ? 1 : 0;   // works for int32 1 and float32 1.0f
        g_mask[i] = v;
    }
}

// Shared layout:
//   xs[b*33 + k]  : 64 b-rows x 32 k (pad 33 -> conflict-free LDS/STS)
//   ws[k*65 + n]  : 32 k-rows x 64 n (pad 65 -> conflict-free LDS/STS)
struct SmemT {
    float xs[64 * 33];
    float ws[32 * 65];
    float mu_s[64];
    unsigned char um_s[64];
};

// One GEMM phase: acc[b_i][gate] += x[b][k] * W[gate*H + j0 + jj][k]
// CTA tile: 64 b x (16 jj x 4 gates), K = kcols (multiple of 32).
// x source: either a global row-major array (base + b*stride + k), or the "label"
// segment built on the fly: use_mu ? mu[b]*W_tgt[k] + b_tgt[k] : emb[b][k].
__device__ __forceinline__ void gemm_phase(
    float (&acc)[8][4],
    const float* __restrict__ xbase, int xstride,
    int lab_mode,
    const float* __restrict__ emb_base, int emb_stride,
    const float* __restrict__ Wt, const float* __restrict__ bt,
    const float* __restrict__ W, int ldW, int kcols,
    int b0, int j0, int tid, int tx, int ty,
    SmemT* sm)
{
    const int ntiles = kcols >> 5;
    float xr[16], wr[16];

    auto load_tile = [&](int kt) {
        const int k0 = kt << 5;
#pragma unroll
        for (int r = 0; r < 16; ++r) {
            int idx = tid + (r << 7);       // 128 threads x 16 = 2048 elems
            int k = idx & 31;
            int q = idx >> 5;               // b for x, n for w
            int kg = k0 + k;
            float xv;
            if (!lab_mode) {
                xv = xbase[(b0 + q) * xstride + kg];
            } else {
                if (sm->um_s[q]) xv = fmaf(sm->mu_s[q], Wt[kg], bt[kg]);
                else             xv = emb_base[(b0 + q) * emb_stride + kg];
            }
            xr[r] = xv;
            int g = q >> 4, jj = q & 15;
            wr[r] = W[(g * Hq + j0 + jj) * ldW + kg];
        }
    };

    load_tile(0);
    for (int kt = 0; kt < ntiles; ++kt) {
        __syncthreads();
#pragma unroll
        for (int r = 0; r < 16; ++r) {
            int idx = tid + (r << 7);
            int k = idx & 31;
            int q = idx >> 5;
            sm->xs[q * 33 + k] = xr[r];
            sm->ws[k * 65 + q] = wr[r];
        }
        __syncthreads();
        if (kt + 1 < ntiles) load_tile(kt + 1);  // overlap next-tile loads with compute
#pragma unroll
        for (int k = 0; k < 32; ++k) {
            float xv[8];
#pragma unroll
            for (int i = 0; i < 8; ++i) xv[i] = sm->xs[(ty * 8 + i) * 33 + k];
#pragma unroll
            for (int g = 0; g < 4; ++g) {
                float wv = sm->ws[k * 65 + g * 16 + tx];
#pragma unroll
                for (int i = 0; i < 8; ++i) acc[i][g] = fmaf(xv[i], wv, acc[i][g]);
            }
        }
    }
}

// Fused epilogue: add biases, LSTM cell update, write c-state and h.
__device__ __forceinline__ void lstm_epilogue(
    float (&acc)[8][4],
    const float* __restrict__ b_ih, const float* __restrict__ b_hh,
    float* __restrict__ c_state, float* __restrict__ h_arr,
    int t, int b0, int j0, int tx, int ty)
{
    float bsum[4];
#pragma unroll
    for (int g = 0; g < 4; ++g) {
        int row = g * Hq + j0 + tx;
        bsum[g] = b_ih[row] + b_hh[row];
    }
    int j = j0 + tx;
#pragma unroll
    for (int i = 0; i < 8; ++i) {
        int bg = b0 + ty * 8 + i;
        float gi = acc[i][0] + bsum[0];
        float gf = acc[i][1] + bsum[1];
        float gg = acc[i][2] + bsum[2];
        float go = acc[i][3] + bsum[3];
        int cidx = bg * Hq + j;
        float cp = (t == 0) ? 0.0f : c_state[cidx];
        float c = sigmoidf_(gf) * cp + sigmoidf_(gi) * tanhf(gg);
        float h = sigmoidf_(go) * tanhf(c);
        c_state[cidx] = c;
        h_arr[(t * Bq + bg) * Hq + j] = h;
    }
}

// ----------------------------- layer-0 cell (one timestep) -----------------------------
__global__ void __launch_bounds__(128) cell0_kernel(
    const float* __restrict__ feat, const float* __restrict__ emb,
    const float* __restrict__ W_ih0, const float* __restrict__ W_hh0,
    const float* __restrict__ b_ih0, const float* __restrict__ b_hh0,
    const float* __restrict__ W_tgt, const float* __restrict__ b_tgt,
    const float* __restrict__ mu_w, const float* __restrict__ mu_b, int t)
{
    __shared__ SmemT sm;
    int tid = threadIdx.x;
    int tx = tid & 15, ty = tid >> 4;
    int jb = blockIdx.x & 63;
    int b0 = (blockIdx.x >> 6) * 64;
    int j0 = jb * 16;

    // use-mu flags for this CTA's 64 batch rows (canonical uint8 mask)
    if (tid < 64) {
        bool um = (t > 0) && (g_mask[(b0 + tid) * Tq + t] != 0);
        sm.um_s[tid] = um ? 1 : 0;
        // NOTE: no zero-init of mu_s here — for t>0 all 64 entries are written
        // by the warp loop below (before the single __syncthreads), and for
        // t==0 mu_s is never read (um_s==0). A concurrent zero-init raced with
        // the warp writes and corrupted the fed-back mu values.
    }

    // mu[b] from previous step's hidden state: hp[b, 2h+l] = h_l[b][h]
    if (t > 0) {
        int wid = tid >> 5, lane = tid & 31;
        const float2* mw2 = reinterpret_cast<const float2*>(mu_w);
        for (int bi = wid; bi < 64; bi += 4) {
            int bg = b0 + bi;
            const float* h0r = g_h0 + ((t - 1) * Bq + bg) * Hq;
            const float* h1r = g_h1 + ((t - 1) * Bq + bg) * Hq;
            float p = 0.0f;
            for (int h = lane; h < Hq; h += 32) {
                float2 m = mw2[h];
                p = fmaf(h0r[h], m.x, p);
                p = fmaf(h1r[h], m.y, p);
            }
#pragma unroll
            for (int o = 16; o; o >>= 1) p += __shfl_xor_sync(0xffffffffu, p, o);
            if (lane == 0) sm.mu_s[bi] = p + mu_b[0];
        }
    }
    __syncthreads();

    float acc[8][4];
#pragma unroll
    for (int i = 0; i < 8; ++i)
#pragma unroll
        for (int g = 0; g < 4; ++g) acc[i][g] = 0.0f;

    // phase A1: feat part  (K = 512), x[b][k] = feat[b][t][k]
    gemm_phase(acc, feat + t * Fq, Tq * Fq, 0, nullptr, 0, nullptr, nullptr,
               W_ih0, IN0q, Fq, b0, j0, tid, tx, ty, &sm);
    // phase A2: label part (K = 64), built on the fly from mask/mu/W_tgt/b_tgt or labels
    gemm_phase(acc, nullptr, 0, 1, emb + t * Eq, Tq * Eq, W_tgt, b_tgt,
               W_ih0 + Fq, IN0q, Eq, b0, j0, tid, tx, ty, &sm);
    // phase B: recurrent part (K = 1024), x = h0(t-1); h0(-1) = 0 -> skip
    if (t > 0)
        gemm_phase(acc, g_h0 + (t - 1) * Bq * Hq, Hq, 0, nullptr, 0, nullptr, nullptr,
                   W_hh0, Hq, Hq, b0, j0, tid, tx, ty, &sm);

    lstm_epilogue(acc, b_ih0, b_hh0, g_c0, g_h0, t, b0, j0, tx, ty);
}

// ----------------------------- layer-1 cell (one timestep) -----------------------------
__global__ void __launch_bounds__(128) cell1_kernel(
    const float* __restrict__ W_ih1, const float* __restrict__ W_hh1,
    const float* __restrict__ b_ih1, const float* __restrict__ b_hh1, int t)
{
    __shared__ SmemT sm;
    int tid = threadIdx.x;
    int tx = tid & 15, ty = tid >> 4;
    int jb = blockIdx.x & 63;
    int b0 = (blockIdx.x >> 6) * 64;
    int j0 = jb * 16;

    float acc[8][4];
#pragma unroll
    for (int i = 0; i < 8; ++i)
#pragma unroll
        for (int g = 0; g < 4; ++g) acc[i][g] = 0.0f;

    // phase A: x = h0(t)  (just written by cell0 for this step)
    gemm_phase(acc, g_h0 + t * Bq * Hq, Hq, 0, nullptr, 0, nullptr, nullptr,
               W_ih1, Hq, Hq, b0, j0, tid, tx, ty, &sm);
    // phase B: x = h1(t-1)
    if (t > 0)
        gemm_phase(acc, g_h1 + (t - 1) * Bq * Hq, Hq, 0, nullptr, 0, nullptr, nullptr,
                   W_hh1, Hq, Hq, b0, j0, tid, tx, ty, &sm);

    lstm_epilogue(acc, b_ih1, b_hh1, g_c1, g_h1, t, b0, j0, tx, ty);
}

// -------------------- final outputs: mu/sigma for all (b, t) in parallel --------------------
__global__ void out_kernel(
    const float* __restrict__ mu_w, const float* __restrict__ mu_b,
    const float* __restrict__ sig_w, const float* __restrict__ sig_b,
    float* __restrict__ out)
{
    int t = blockIdx.x;
    int wid = threadIdx.x >> 5, lane = threadIdx.x & 31;
    const float2* mw2 = reinterpret_cast<const float2*>(mu_w);
    const float2* sw2 = reinterpret_cast<const float2*>(sig_w);
    for (int b = wid; b < Bq; b += 8) {
        const float* h0r = g_h0 + (t * Bq + b) * Hq;
        const float* h1r = g_h1 + (t * Bq + b) * Hq;
        float mp = 0.0f, sp = 0.0f;
        for (int h = lane; h < Hq; h += 32) {
            float a = h0r[h], c = h1r[h];
            float2 m = mw2[h];
            float2 s = sw2[h];
            mp = fmaf(a, m.x, fmaf(c, m.y, mp));
            sp = fmaf(a, s.x, fmaf(c, s.y, sp));
        }
#pragma unroll
        for (int o = 16; o; o >>= 1) {
            mp += __shfl_xor_sync(0xffffffffu, mp, o);
            sp += __shfl_xor_sync(0xffffffffu, sp, o);
        }
        if (lane == 0) {
            float mu = mp + mu_b[0];
            float sv = sp + sig_b[0];
            // stable softplus matching jax.nn.softplus
            float sig = fmaxf(sv, 0.0f) + log1pf(expf(-fabsf(sv)));
            out[(b * Tq + t) * 2 + 0] = mu;
            out[(b * Tq + t) * 2 + 1] = sig;
        }
    }
}

// ----------------------------------- launch -----------------------------------
extern "C" void kernel_launch(void* const* d_in, const int* in_sizes, int n_in,
                              void* d_out, int out_size)
{
    const float* feat  = (const float*)d_in[0];
    const float* emb   = (const float*)d_in[1];
    const unsigned char* mask_raw = (const unsigned char*)d_in[2];
    const float* W_ih0 = (const float*)d_in[3];
    const float* W_hh0 = (const float*)d_in[4];
    const float* b_ih0 = (const float*)d_in[5];
    const float* b_hh0 = (const float*)d_in[6];
    const float* W_ih1 = (const float*)d_in[7];
    const float* W_hh1 = (const float*)d_in[8];
    const float* b_ih1 = (const float*)d_in[9];
    const float* b_hh1 = (const float*)d_in[10];
    const float* W_tgt = (const float*)d_in[11];
    const float* b_tgt = (const float*)d_in[12];
    const float* mu_w  = (const float*)d_in[13];
    const float* mu_b  = (const float*)d_in[14];
    const float* sig_w = (const float*)d_in[15];
    const float* sig_b = (const float*)d_in[16];
    float* out = (float*)d_out;

    mask_norm_kernel<<<1, 1024>>>(mask_raw);
    for (int t = 0; t < Tq; ++t) {
        cell0_kernel<<<128, 128>>>(feat, emb, W_ih0, W_hh0, b_ih0, b_hh0,
                                   W_tgt, b_tgt, mu_w, mu_b, t);
        cell1_kernel<<<128, 128>>>(W_ih1, W_hh1, b_ih1, b_hh1, t);
    }
    out_kernel<<<Tq, 256>>>(mu_w, mu_b, sig_w, sig_b, out);
}